// round 4
// baseline (speedup 1.0000x reference)
#include <cuda_runtime.h>
#include <math.h>

#define B_ROWS 65536
#define C_CLS  1000
#define C4     250        // 1000 floats = 250 float4 per row
#define BETA_F 3.0f
#define DOT_BLOCKS 256

// ---- scratch (no allocations allowed) ----
__device__ int   g_counts[C_CLS * C_CLS];
__device__ float g_glp[B_ROWS];
__device__ int   g_pred[B_ROWS];
__device__ float g_scale[C_CLS];
__device__ float g_partial[DOT_BLOCKS];
__device__ int   g_is64;

// ---------------------------------------------------------------------------
// k0: zero the counts matrix and detect targets dtype (int32 vs int64).
// For int64 little-endian values in [0,1000), every odd 32-bit word is 0.
// ---------------------------------------------------------------------------
__global__ void k_zero(const int* __restrict__ tgt_words) {
    int i = blockIdx.x * blockDim.x + threadIdx.x;
    int stride = gridDim.x * blockDim.x;
    for (int j = i; j < C_CLS * C_CLS; j += stride) g_counts[j] = 0;
    if (i == 0) {
        int nz = 0;
        #pragma unroll 1
        for (int k = 1; k < 256; k += 2) nz |= tgt_words[k];
        g_is64 = (nz == 0) ? 1 : 0;
    }
}

// ---------------------------------------------------------------------------
// k1: one warp per row. Fused rowmax + argmax + sumexp + target-logit gather
// + scatter-count. 262 MB streamed once -> HBM-bound.
// ---------------------------------------------------------------------------
__global__ __launch_bounds__(256) void k_rows(
    const float* __restrict__ outp, const void* __restrict__ tgt)
{
    int warp = (blockIdx.x * 256 + threadIdx.x) >> 5;
    int lane = threadIdx.x & 31;
    if (warp >= B_ROWS) return;

    const float4* rp = (const float4*)(outp + (size_t)warp * C_CLS);

    float vals[32];
    float m  = -INFINITY;
    int   am = 0x7fffffff;

    // Batch 8 independent LDG.128 per lane (MLP), track lane-local max/argmax.
    #pragma unroll
    for (int i = 0; i < 8; i++) {
        int idx4 = lane + i * 32;
        float4 v;
        if (idx4 < C4) v = rp[idx4];
        else           v = make_float4(-INFINITY, -INFINITY, -INFINITY, -INFINITY);
        int base = idx4 * 4;
        vals[4*i+0] = v.x; vals[4*i+1] = v.y; vals[4*i+2] = v.z; vals[4*i+3] = v.w;
        if (v.x > m || (v.x == m && base + 0 < am)) { m = v.x; am = base + 0; }
        if (v.y > m || (v.y == m && base + 1 < am)) { m = v.y; am = base + 1; }
        if (v.z > m || (v.z == m && base + 2 < am)) { m = v.z; am = base + 2; }
        if (v.w > m || (v.w == m && base + 3 < am)) { m = v.w; am = base + 3; }
    }

    // Warp argmax-reduce (first-index tiebreak, matches jnp.argmax).
    #pragma unroll
    for (int off = 16; off; off >>= 1) {
        float om = __shfl_down_sync(0xffffffffu, m,  off);
        int   oa = __shfl_down_sync(0xffffffffu, am, off);
        if (om > m || (om == m && oa < am)) { m = om; am = oa; }
    }
    m  = __shfl_sync(0xffffffffu, m,  0);
    am = __shfl_sync(0xffffffffu, am, 0);

    // Sumexp over register-resident values (padding -INF -> exp = 0).
    float s = 0.0f;
    #pragma unroll
    for (int k = 0; k < 32; k++) s += __expf(vals[k] - m);
    #pragma unroll
    for (int off = 16; off; off >>= 1)
        s += __shfl_down_sync(0xffffffffu, s, off);

    if (lane == 0) {
        long long t = g_is64 ? ((const long long*)tgt)[warp]
                             : (long long)((const int*)tgt)[warp];
        float xt  = outp[(size_t)warp * C_CLS + (int)t];
        float glp = xt - m - __logf(s);
        g_glp[warp]  = glp;
        g_pred[warp] = am;
        atomicAdd(&g_counts[(int)t * C_CLS + am], 1);
    }
}

// ---------------------------------------------------------------------------
// k2: per-class row-sum of (cost_matrix + counts) -> scale[t] = beta/max(1,sum)
// One block per class row.
// ---------------------------------------------------------------------------
__global__ __launch_bounds__(256) void k_scale(const float* __restrict__ cost) {
    int r = blockIdx.x;
    float s = 0.0f;
    for (int c = threadIdx.x; c < C_CLS; c += 256) {
        int idx = r * C_CLS + c;
        s += cost[idx] + (float)g_counts[idx];
    }
    __shared__ float sh[256];
    sh[threadIdx.x] = s;
    __syncthreads();
    #pragma unroll
    for (int off = 128; off; off >>= 1) {
        if (threadIdx.x < off) sh[threadIdx.x] += sh[threadIdx.x + off];
        __syncthreads();
    }
    if (threadIdx.x == 0) g_scale[r] = BETA_F / fmaxf(1.0f, sh[0]);
}

// ---------------------------------------------------------------------------
// k3: per-sample gather + product, block tree-reduce to partials.
// Grid of 256x256 = exactly one thread per sample -> deterministic.
// ---------------------------------------------------------------------------
__global__ __launch_bounds__(256) void k_dot(
    const float* __restrict__ cost, const void* __restrict__ tgt)
{
    int b = blockIdx.x * 256 + threadIdx.x;
    float acc = 0.0f;
    if (b < B_ROWS) {
        long long t = g_is64 ? ((const long long*)tgt)[b]
                             : (long long)((const int*)tgt)[b];
        int p   = g_pred[b];
        int idx = (int)t * C_CLS + p;
        float cm = cost[idx] + (float)g_counts[idx];
        acc = g_glp[b] * cm * g_scale[(int)t];
    }
    __shared__ float sh[256];
    sh[threadIdx.x] = acc;
    __syncthreads();
    #pragma unroll
    for (int off = 128; off; off >>= 1) {
        if (threadIdx.x < off) sh[threadIdx.x] += sh[threadIdx.x + off];
        __syncthreads();
    }
    if (threadIdx.x == 0) g_partial[blockIdx.x] = sh[0];
}

// ---------------------------------------------------------------------------
// k4: final deterministic reduce of 256 partials -> -mean
// ---------------------------------------------------------------------------
__global__ __launch_bounds__(DOT_BLOCKS) void k_final(float* __restrict__ out) {
    __shared__ float sh[DOT_BLOCKS];
    sh[threadIdx.x] = g_partial[threadIdx.x];
    __syncthreads();
    #pragma unroll
    for (int off = DOT_BLOCKS / 2; off; off >>= 1) {
        if (threadIdx.x < off) sh[threadIdx.x] += sh[threadIdx.x + off];
        __syncthreads();
    }
    if (threadIdx.x == 0) out[0] = -sh[0] / (float)B_ROWS;
}

extern "C" void kernel_launch(void* const* d_in, const int* in_sizes, int n_in,
                              void* d_out, int out_size) {
    const float* outputs = (const float*)d_in[0];
    const void*  targets = d_in[1];
    const float* cost    = (const float*)d_in[2];
    float* out = (float*)d_out;

    k_zero <<<1024, 256>>>((const int*)targets);
    k_rows <<<B_ROWS / 8, 256>>>(outputs, targets);      // 8 warps/block
    k_scale<<<C_CLS, 256>>>(cost);
    k_dot  <<<DOT_BLOCKS, 256>>>(cost, targets);
    k_final<<<1, DOT_BLOCKS>>>(out);
}

// round 5
// speedup vs baseline: 1.0424x; 1.0424x over previous
#include <cuda_runtime.h>
#include <math.h>

#define B_ROWS 65536
#define C_CLS  1000
#define C4     250        // 1000 floats = 250 float4 per row
#define BETA_F 3.0f
#define DOT_BLOCKS 256

// ---- scratch (no allocations allowed) ----
__device__ int   g_counts[C_CLS * C_CLS];
__device__ float g_glp[B_ROWS];
__device__ int   g_pred[B_ROWS];
__device__ float g_scale[C_CLS];
__device__ float g_partial[DOT_BLOCKS];
__device__ int   g_is64;

// ---------------------------------------------------------------------------
// k0: zero the counts matrix and detect targets dtype (int32 vs int64).
// For int64 little-endian values in [0,1000), every odd 32-bit word is 0.
// ---------------------------------------------------------------------------
__global__ void k_zero(const int* __restrict__ tgt_words) {
    int i = blockIdx.x * blockDim.x + threadIdx.x;
    int stride = gridDim.x * blockDim.x;
    for (int j = i; j < C_CLS * C_CLS; j += stride) g_counts[j] = 0;
    if (i == 0) {
        int nz = 0;
        #pragma unroll 1
        for (int k = 1; k < 256; k += 2) nz |= tgt_words[k];
        g_is64 = (nz == 0) ? 1 : 0;
    }
}

// ---------------------------------------------------------------------------
// k1: one warp per row. Fused rowmax + argmax + sumexp + target-logit gather
// + scatter-count. 262 MB streamed once -> HBM-bound.
// ---------------------------------------------------------------------------
__global__ __launch_bounds__(256) void k_rows(
    const float* __restrict__ outp, const void* __restrict__ tgt)
{
    int warp = (blockIdx.x * 256 + threadIdx.x) >> 5;
    int lane = threadIdx.x & 31;
    if (warp >= B_ROWS) return;

    const float4* rp = (const float4*)(outp + (size_t)warp * C_CLS);

    float vals[32];
    float m  = -INFINITY;
    int   am = 0x7fffffff;

    // Batch 8 independent LDG.128 per lane (MLP), track lane-local max/argmax.
    #pragma unroll
    for (int i = 0; i < 8; i++) {
        int idx4 = lane + i * 32;
        float4 v;
        if (idx4 < C4) v = rp[idx4];
        else           v = make_float4(-INFINITY, -INFINITY, -INFINITY, -INFINITY);
        int base = idx4 * 4;
        vals[4*i+0] = v.x; vals[4*i+1] = v.y; vals[4*i+2] = v.z; vals[4*i+3] = v.w;
        if (v.x > m || (v.x == m && base + 0 < am)) { m = v.x; am = base + 0; }
        if (v.y > m || (v.y == m && base + 1 < am)) { m = v.y; am = base + 1; }
        if (v.z > m || (v.z == m && base + 2 < am)) { m = v.z; am = base + 2; }
        if (v.w > m || (v.w == m && base + 3 < am)) { m = v.w; am = base + 3; }
    }

    // Warp argmax-reduce (first-index tiebreak, matches jnp.argmax).
    #pragma unroll
    for (int off = 16; off; off >>= 1) {
        float om = __shfl_down_sync(0xffffffffu, m,  off);
        int   oa = __shfl_down_sync(0xffffffffu, am, off);
        if (om > m || (om == m && oa < am)) { m = om; am = oa; }
    }
    m  = __shfl_sync(0xffffffffu, m,  0);
    am = __shfl_sync(0xffffffffu, am, 0);

    // Sumexp over register-resident values (padding -INF -> exp = 0).
    float s = 0.0f;
    #pragma unroll
    for (int k = 0; k < 32; k++) s += __expf(vals[k] - m);
    #pragma unroll
    for (int off = 16; off; off >>= 1)
        s += __shfl_down_sync(0xffffffffu, s, off);

    if (lane == 0) {
        long long t = g_is64 ? ((const long long*)tgt)[warp]
                             : (long long)((const int*)tgt)[warp];
        float xt  = outp[(size_t)warp * C_CLS + (int)t];
        float glp = xt - m - __logf(s);
        g_glp[warp]  = glp;
        g_pred[warp] = am;
        atomicAdd(&g_counts[(int)t * C_CLS + am], 1);
    }
}

// ---------------------------------------------------------------------------
// k2: per-class row-sum of (cost_matrix + counts) -> scale[t] = beta/max(1,sum)
// One block per class row.
// ---------------------------------------------------------------------------
__global__ __launch_bounds__(256) void k_scale(const float* __restrict__ cost) {
    int r = blockIdx.x;
    float s = 0.0f;
    for (int c = threadIdx.x; c < C_CLS; c += 256) {
        int idx = r * C_CLS + c;
        s += cost[idx] + (float)g_counts[idx];
    }
    __shared__ float sh[256];
    sh[threadIdx.x] = s;
    __syncthreads();
    #pragma unroll
    for (int off = 128; off; off >>= 1) {
        if (threadIdx.x < off) sh[threadIdx.x] += sh[threadIdx.x + off];
        __syncthreads();
    }
    if (threadIdx.x == 0) g_scale[r] = BETA_F / fmaxf(1.0f, sh[0]);
}

// ---------------------------------------------------------------------------
// k3: per-sample gather + product, block tree-reduce to partials.
// Grid of 256x256 = exactly one thread per sample -> deterministic.
// ---------------------------------------------------------------------------
__global__ __launch_bounds__(256) void k_dot(
    const float* __restrict__ cost, const void* __restrict__ tgt)
{
    int b = blockIdx.x * 256 + threadIdx.x;
    float acc = 0.0f;
    if (b < B_ROWS) {
        long long t = g_is64 ? ((const long long*)tgt)[b]
                             : (long long)((const int*)tgt)[b];
        int p   = g_pred[b];
        int idx = (int)t * C_CLS + p;
        float cm = cost[idx] + (float)g_counts[idx];
        acc = g_glp[b] * cm * g_scale[(int)t];
    }
    __shared__ float sh[256];
    sh[threadIdx.x] = acc;
    __syncthreads();
    #pragma unroll
    for (int off = 128; off; off >>= 1) {
        if (threadIdx.x < off) sh[threadIdx.x] += sh[threadIdx.x + off];
        __syncthreads();
    }
    if (threadIdx.x == 0) g_partial[blockIdx.x] = sh[0];
}

// ---------------------------------------------------------------------------
// k4: final deterministic reduce of 256 partials -> -mean
// ---------------------------------------------------------------------------
__global__ __launch_bounds__(DOT_BLOCKS) void k_final(float* __restrict__ out) {
    __shared__ float sh[DOT_BLOCKS];
    sh[threadIdx.x] = g_partial[threadIdx.x];
    __syncthreads();
    #pragma unroll
    for (int off = DOT_BLOCKS / 2; off; off >>= 1) {
        if (threadIdx.x < off) sh[threadIdx.x] += sh[threadIdx.x + off];
        __syncthreads();
    }
    if (threadIdx.x == 0) out[0] = -sh[0] / (float)B_ROWS;
}

extern "C" void kernel_launch(void* const* d_in, const int* in_sizes, int n_in,
                              void* d_out, int out_size) {
    const float* outputs = (const float*)d_in[0];
    const void*  targets = d_in[1];
    const float* cost    = (const float*)d_in[2];
    float* out = (float*)d_out;

    k_zero <<<1024, 256>>>((const int*)targets);
    k_rows <<<B_ROWS / 8, 256>>>(outputs, targets);      // 8 warps/block
    k_scale<<<C_CLS, 256>>>(cost);
    k_dot  <<<DOT_BLOCKS, 256>>>(cost, targets);
    k_final<<<1, DOT_BLOCKS>>>(out);
}